// round 13
// baseline (speedup 1.0000x reference)
#include <cuda_runtime.h>
#include <cuda_fp16.h>
#include <math.h>
#include <stdint.h>

// Problem constants
#define BB 8
#define FF 16
#define NN 2048
#define JS 4
#define NCOLS 21
#define OUT_ELEMS (BB*FF*NCOLS)
#define NW2 1024                 // packed fp16-pair words per row

// ---------------- packed hi/lo scratch (uint32 = 2 x fp16) ----------------
__device__ __align__(256) uint32_t g_X2h[BB*FF*NW2], g_X2l[BB*FF*NW2];
__device__ __align__(256) uint32_t g_P2h[(size_t)JS*NN*NW2];
__device__ __align__(256) uint32_t g_P2l[(size_t)JS*NN*NW2];
__device__ __align__(256) uint32_t g_S2h[(size_t)BB*JS*FF*NW2];
__device__ __align__(256) uint32_t g_S2l[(size_t)BB*JS*FF*NW2];

// ---------------- helpers ----------------
__device__ __forceinline__ uint32_t smem_u32(const void* p) {
    uint32_t a;
    asm("{ .reg .u64 t; cvta.to.shared.u64 t, %1; cvt.u32.u64 %0, t; }" : "=r"(a) : "l"(p));
    return a;
}
__device__ __forceinline__ void cp16(uint32_t s, const void* g) {
    asm volatile("cp.async.cg.shared.global [%0], [%1], 16;\n" :: "r"(s), "l"(g));
}
__device__ __forceinline__ uint32_t pack2(float a, float b) {
    __half2 h = __floats2half2_rn(a, b);
    return *reinterpret_cast<uint32_t*>(&h);
}
#define MMA_F16(C, A, B0, B1)                                                 \
    asm volatile(                                                             \
        "mma.sync.aligned.m16n8k16.row.col.f32.f16.f16.f32 "                  \
        "{%0,%1,%2,%3}, {%4,%5,%6,%7}, {%8,%9}, {%0,%1,%2,%3};\n"             \
        : "+f"((C)[0]), "+f"((C)[1]), "+f"((C)[2]), "+f"((C)[3])              \
        : "r"((A)[0]), "r"((A)[1]), "r"((A)[2]), "r"((A)[3]), "r"(B0), "r"(B1))
#define LDSM4(R, addr)                                                        \
    asm volatile("ldmatrix.sync.aligned.m8n8.x4.shared.b16 {%0,%1,%2,%3}, [%4];" \
        : "=r"((R)[0]), "=r"((R)[1]), "=r"((R)[2]), "=r"((R)[3]) : "r"(addr))

// ---------------- fused prep: phi0 + phi-zero + x hi/lo split ----------------
__global__ void prep_kernel(const float* __restrict__ x, const float* __restrict__ lp,
                            float* __restrict__ out) {
    const int r = blockIdx.x, tid = threadIdx.x;
    const float2* x2 = (const float2*)(x) + (size_t)r * NW2;
    const float2* lp2 = (const float2*)lp;
    float s = 0.0f;
    #pragma unroll
    for (int it = 0; it < 4; it++) {
        int wd = it * 256 + tid;
        float2 v = x2[wd];
        float2 l = lp2[wd];
        s += v.x * l.x + v.y * l.y;
        float ah = __half2float(__float2half_rn(v.x));
        float bh = __half2float(__float2half_rn(v.y));
        g_X2h[r * NW2 + wd] = pack2(v.x, v.y);
        g_X2l[r * NW2 + wd] = pack2(v.x - ah, v.y - bh);
    }
    if (tid >= 1 && tid < NCOLS) out[r * NCOLS + tid] = 0.0f;
    __shared__ float red[8];
    #pragma unroll
    for (int o = 16; o; o >>= 1) s += __shfl_xor_sync(0xffffffffu, s, o);
    if ((tid & 31) == 0) red[tid >> 5] = s;
    __syncthreads();
    if (tid < 8) {
        s = red[tid];
        #pragma unroll
        for (int o = 4; o; o >>= 1) s += __shfl_xor_sync(0xffu, s, o);
        if (tid == 0) out[r * NCOLS + 0] = s;
    }
}

// ---------------- psi transpose+split (R10 wide-IO version) ----------------
__global__ void transpose_pack_psi(const float* __restrict__ psi) {
    __shared__ float sm[32][33];
    const int j = blockIdx.z;
    const int m0 = blockIdx.x * 32, n0 = blockIdx.y * 32;
    const int tid = threadIdx.x;
    const float* P = psi + (size_t)j * NN * NN;
    {
        int nl = tid >> 3, c4 = tid & 7;
        float4 v = *(const float4*)&P[(size_t)(n0 + nl) * NN + m0 + c4 * 4];
        sm[nl][c4 * 4 + 0] = v.x;
        sm[nl][c4 * 4 + 1] = v.y;
        sm[nl][c4 * 4 + 2] = v.z;
        sm[nl][c4 * 4 + 3] = v.w;
    }
    __syncthreads();
    {
        int ml = tid >> 3, p = tid & 7;
        float a0 = sm[4 * p + 0][ml], a1 = sm[4 * p + 1][ml];
        float a2 = sm[4 * p + 2][ml], a3 = sm[4 * p + 3][ml];
        float h0 = __half2float(__float2half_rn(a0));
        float h1 = __half2float(__float2half_rn(a1));
        float h2 = __half2float(__float2half_rn(a2));
        float h3 = __half2float(__float2half_rn(a3));
        size_t o = (size_t)j * NN * NW2 + (size_t)(m0 + ml) * NW2 + (n0 >> 1) + 2 * p;
        *(uint2*)&g_P2h[o] = make_uint2(pack2(a0, a1), pack2(a2, a3));
        *(uint2*)&g_P2l[o] = make_uint2(pack2(a0 - h0, a1 - h1), pack2(a2 - h2, a3 - h3));
    }
}

// ---------------- fused fp16 3-term tensor GEMM ----------------
// Tile 128 x TN (TN=16*NI), BK=32, 256 thr, 8 warps (4M x 2N).
// smem planes (Ah,Al,Bh,Bl), 80 B/row: ldmatrix conflict-free.
// R13: NI=4 both layers, occupancy 3 CTAs/SM (24 warps) to test H1.
template <int LAYER, int NI>
__global__ __launch_bounds__(256, (NI <= 4 ? 3 : 2))
void gemm_f16(const float* __restrict__ lp, float* __restrict__ phi) {
    constexpr int TN  = NI * 16;
    constexpr int APL = 128 * 80;            // A plane bytes
    constexpr int BPL = TN * 80;             // B plane bytes
    constexpr int STB = 2 * APL + 2 * BPL;   // stage bytes
    constexpr int NKC = 64;                  // 2048/32 k-chunks

    extern __shared__ __align__(1024) char smc[];
    const uint32_t sb = smem_u32(smc);
    const int tid = threadIdx.x;
    const int lane = tid & 31, w = tid >> 5;
    const int wm = w & 3, wn = w >> 2;
    const int g = lane >> 2, t = lane & 3;
    const int j  = blockIdx.z;
    const int n0 = blockIdx.x * TN, m0 = blockIdx.y * 128;

    const uint32_t* srcs[4] = {
        ((LAYER == 1) ? g_X2h : g_S2h) + (size_t)m0 * NW2,
        ((LAYER == 1) ? g_X2l : g_S2l) + (size_t)m0 * NW2,
        g_P2h + (size_t)j * NN * NW2 + (size_t)n0 * NW2,
        g_P2l + (size_t)j * NN * NW2 + (size_t)n0 * NW2 };

    const int lrow = lane & 7, lm = lane >> 3;
    uint32_t aoff[2];
    #pragma unroll
    for (int mi = 0; mi < 2; mi++)
        aoff[mi] = (uint32_t)((wm * 32 + mi * 16 + (lm & 1) * 8 + lrow) * 80
                              + (lm >> 1) * 16);
    const uint32_t boff = (uint32_t)((wn * NI * 8 + (lm >> 1) * 8 + lrow) * 80
                                     + (lm & 1) * 16);

    auto copy_stage = [&](int buf, int kc) {
        uint32_t st = sb + buf * STB;
        #pragma unroll
        for (int pl = 0; pl < 2; pl++) {                 // A planes: 128 rows
            uint32_t pb = st + pl * APL;
            const uint32_t* s = srcs[pl] + kc * 16;
            #pragma unroll
            for (int i = 0; i < 2; i++) {
                int cid = i * 256 + tid, row = cid >> 2, cc = cid & 3;
                cp16(pb + row * 80 + cc * 16, s + (size_t)row * NW2 + cc * 4);
            }
        }
        constexpr int BPC = (TN * 4) / 256;              // 1 for NI=4
        #pragma unroll
        for (int pl = 0; pl < 2; pl++) {                 // B planes: TN rows
            uint32_t pb = st + 2 * APL + pl * BPL;
            const uint32_t* s = srcs[2 + pl] + kc * 16;
            #pragma unroll
            for (int i = 0; i < BPC; i++) {
                int cid = i * 256 + tid, row = cid >> 2, cc = cid & 3;
                cp16(pb + row * 80 + cc * 16, s + (size_t)row * NW2 + cc * 4);
            }
        }
        asm volatile("cp.async.commit_group;\n");
    };

    float c[2][NI][4] = {};

    copy_stage(0, 0);
    for (int kt = 0; kt < NKC; kt++) {
        const int buf = kt & 1;
        if (kt + 1 < NKC) {
            copy_stage(buf ^ 1, kt + 1);
            asm volatile("cp.async.wait_group 1;\n");
        } else {
            asm volatile("cp.async.wait_group 0;\n");
        }
        __syncthreads();

        const uint32_t st = sb + buf * STB;
        #pragma unroll
        for (int kk = 0; kk < 2; kk++) {
            const uint32_t kb = kk * 32;
            uint32_t ah[2][4], al[2][4], bh[NI / 2][4];
            LDSM4(ah[0], st + aoff[0] + kb);
            LDSM4(ah[1], st + aoff[1] + kb);
            LDSM4(al[0], st + APL + aoff[0] + kb);
            LDSM4(al[1], st + APL + aoff[1] + kb);
            #pragma unroll
            for (int q = 0; q < NI / 2; q++)
                LDSM4(bh[q], st + 2 * APL + boff + q * 1280 + kb);

            #pragma unroll
            for (int ni = 0; ni < NI; ni++) {    // term 0: Al x Bh
                uint32_t b0 = bh[ni >> 1][(ni & 1) * 2], b1 = bh[ni >> 1][(ni & 1) * 2 + 1];
                MMA_F16(c[0][ni], al[0], b0, b1);
                MMA_F16(c[1][ni], al[1], b0, b1);
            }
            #pragma unroll
            for (int q = 0; q < NI / 2; q++) {   // term 1: Ah x Bl (streamed)
                uint32_t bl[4];
                LDSM4(bl, st + 2 * APL + BPL + boff + q * 1280 + kb);
                #pragma unroll
                for (int s = 0; s < 2; s++) {
                    MMA_F16(c[0][q * 2 + s], ah[0], bl[s * 2], bl[s * 2 + 1]);
                    MMA_F16(c[1][q * 2 + s], ah[1], bl[s * 2], bl[s * 2 + 1]);
                }
            }
            #pragma unroll
            for (int ni = 0; ni < NI; ni++) {    // term 2: Ah x Bh
                uint32_t b0 = bh[ni >> 1][(ni & 1) * 2], b1 = bh[ni >> 1][(ni & 1) * 2 + 1];
                MMA_F16(c[0][ni], ah[0], b0, b1);
                MMA_F16(c[1][ni], ah[1], b0, b1);
            }
        }
        __syncthreads();
    }

    // Epilogue: abs + lowpass partials; layer-1 packs S1 hi/lo.
    float p[2][2] = {};
    #pragma unroll
    for (int mi = 0; mi < 2; mi++) {
        #pragma unroll
        for (int ni = 0; ni < NI; ni++) {
            const int m = n0 + wn * NI * 8 + ni * 8 + 2 * t;
            float v0 = fabsf(c[mi][ni][0]), v1 = fabsf(c[mi][ni][1]);
            float v2 = fabsf(c[mi][ni][2]), v3 = fabsf(c[mi][ni][3]);
            float l0 = __ldg(&lp[m]), l1 = __ldg(&lp[m + 1]);
            p[mi][0] += v0 * l0 + v1 * l1;
            p[mi][1] += v2 * l0 + v3 * l1;
            if (LAYER == 1) {
                const int r0 = m0 + wm * 32 + mi * 16 + g;
                const int r1 = r0 + 8;
                int s0 = (((r0 >> 4) * JS + j) << 4) + (r0 & 15);
                int s1 = (((r1 >> 4) * JS + j) << 4) + (r1 & 15);
                float h0 = __half2float(__float2half_rn(v0));
                float h1 = __half2float(__float2half_rn(v1));
                float h2 = __half2float(__float2half_rn(v2));
                float h3 = __half2float(__float2half_rn(v3));
                g_S2h[(size_t)s0 * NW2 + (m >> 1)] = pack2(v0, v1);
                g_S2l[(size_t)s0 * NW2 + (m >> 1)] = pack2(v0 - h0, v1 - h1);
                g_S2h[(size_t)s1 * NW2 + (m >> 1)] = pack2(v2, v3);
                g_S2l[(size_t)s1 * NW2 + (m >> 1)] = pack2(v2 - h2, v3 - h3);
            }
        }
    }
    #pragma unroll
    for (int mi = 0; mi < 2; mi++) {
        #pragma unroll
        for (int s = 0; s < 2; s++) {
            float v = p[mi][s];
            v += __shfl_xor_sync(0xffffffffu, v, 1);
            v += __shfl_xor_sync(0xffffffffu, v, 2);
            if (t == 0) {
                const int r = m0 + wm * 32 + mi * 16 + g + s * 8;
                int b, f, col;
                if (LAYER == 1) { b = r >> 4; f = r & 15; col = 1 + j; }
                else { b = r >> 6; int j1 = (r >> 4) & 3; f = r & 15; col = 5 + j1 * 4 + j; }
                atomicAdd(&phi[(b * FF + f) * NCOLS + col], v);
            }
        }
    }
}

// ---------------- launch ----------------
extern "C" void kernel_launch(void* const* d_in, const int* in_sizes, int n_in,
                              void* d_out, int out_size) {
    const float* x   = (const float*)d_in[0];   // (8,16,2048)
    const float* psi = (const float*)d_in[1];   // (4,2048,2048)
    const float* lp  = (const float*)d_in[2];   // (2048,)
    float* out = (float*)d_out;                 // (8,16,21)
    (void)in_sizes; (void)n_in; (void)out_size;

    constexpr int SM14 = 2 * (2 * 128 * 80 + 2 * 64 * 80);   // 61440 (NI=4)
    cudaFuncSetAttribute(gemm_f16<1, 4>, cudaFuncAttributeMaxDynamicSharedMemorySize, SM14);
    cudaFuncSetAttribute(gemm_f16<2, 4>, cudaFuncAttributeMaxDynamicSharedMemorySize, SM14);

    prep_kernel<<<BB * FF, 256>>>(x, lp, out);
    transpose_pack_psi<<<dim3(64, 64, JS), 256>>>(psi);
    // layer 1: TN=64 -> 32 N-tiles x 1 M-tile x 4 j = 128 CTAs
    gemm_f16<1, 4><<<dim3(32, 1, 4), 256, SM14>>>(lp, out);
    // layer 2: TN=64 -> 32 N-tiles x 4 M-tiles x 4 j = 512 CTAs, occ 3
    gemm_f16<2, 4><<<dim3(32, 4, 4), 256, SM14>>>(lp, out);
}

// round 14
// speedup vs baseline: 1.1039x; 1.1039x over previous
#include <cuda_runtime.h>
#include <cuda_fp16.h>
#include <math.h>
#include <stdint.h>

// Problem constants
#define BB 8
#define FF 16
#define NN 2048
#define JS 4
#define NCOLS 21
#define OUT_ELEMS (BB*FF*NCOLS)
#define NW2 1024                 // packed fp16-pair words per row

// ---------------- scratch ----------------
__device__ __align__(256) uint32_t g_X2h[BB*FF*NW2], g_X2l[BB*FF*NW2];
__device__ __align__(256) uint32_t g_P2h[(size_t)JS*NN*NW2];
__device__ __align__(256) uint32_t g_P2l[(size_t)JS*NN*NW2];
__device__ __align__(256) uint32_t g_S2h[(size_t)BB*JS*FF*NW2];
__device__ __align__(256) uint32_t g_S2l[(size_t)BB*JS*FF*NW2];
__device__ __align__(256) float    g_S1f[2 * 512 * NN];     // split-K partials (8 MB)

// ---------------- helpers ----------------
__device__ __forceinline__ uint32_t smem_u32(const void* p) {
    uint32_t a;
    asm("{ .reg .u64 t; cvta.to.shared.u64 t, %1; cvt.u32.u64 %0, t; }" : "=r"(a) : "l"(p));
    return a;
}
__device__ __forceinline__ void cp16(uint32_t s, const void* g) {
    asm volatile("cp.async.cg.shared.global [%0], [%1], 16;\n" :: "r"(s), "l"(g));
}
__device__ __forceinline__ uint32_t pack2(float a, float b) {
    __half2 h = __floats2half2_rn(a, b);
    return *reinterpret_cast<uint32_t*>(&h);
}
#define MMA_F16(C, A, B0, B1)                                                 \
    asm volatile(                                                             \
        "mma.sync.aligned.m16n8k16.row.col.f32.f16.f16.f32 "                  \
        "{%0,%1,%2,%3}, {%4,%5,%6,%7}, {%8,%9}, {%0,%1,%2,%3};\n"             \
        : "+f"((C)[0]), "+f"((C)[1]), "+f"((C)[2]), "+f"((C)[3])              \
        : "r"((A)[0]), "r"((A)[1]), "r"((A)[2]), "r"((A)[3]), "r"(B0), "r"(B1))
#define LDSM4(R, addr)                                                        \
    asm volatile("ldmatrix.sync.aligned.m8n8.x4.shared.b16 {%0,%1,%2,%3}, [%4];" \
        : "=r"((R)[0]), "=r"((R)[1]), "=r"((R)[2]), "=r"((R)[3]) : "r"(addr))

// ---------------- fused prep: phi0 + phi-zero + x hi/lo split ----------------
__global__ void prep_kernel(const float* __restrict__ x, const float* __restrict__ lp,
                            float* __restrict__ out) {
    const int r = blockIdx.x, tid = threadIdx.x;
    const float2* x2 = (const float2*)(x) + (size_t)r * NW2;
    const float2* lp2 = (const float2*)lp;
    float s = 0.0f;
    #pragma unroll
    for (int it = 0; it < 4; it++) {
        int wd = it * 256 + tid;
        float2 v = x2[wd];
        float2 l = lp2[wd];
        s += v.x * l.x + v.y * l.y;
        float ah = __half2float(__float2half_rn(v.x));
        float bh = __half2float(__float2half_rn(v.y));
        g_X2h[r * NW2 + wd] = pack2(v.x, v.y);
        g_X2l[r * NW2 + wd] = pack2(v.x - ah, v.y - bh);
    }
    if (tid >= 5 && tid < NCOLS) out[r * NCOLS + tid] = 0.0f;  // zero cols 5..20 (gemm2 atomics)
    __shared__ float red[8];
    #pragma unroll
    for (int o = 16; o; o >>= 1) s += __shfl_xor_sync(0xffffffffu, s, o);
    if ((tid & 31) == 0) red[tid >> 5] = s;
    __syncthreads();
    if (tid < 8) {
        s = red[tid];
        #pragma unroll
        for (int o = 4; o; o >>= 1) s += __shfl_xor_sync(0xffu, s, o);
        if (tid == 0) out[r * NCOLS + 0] = s;
    }
}

// ---------------- psi transpose+split (R10 wide-IO version) ----------------
__global__ void transpose_pack_psi(const float* __restrict__ psi) {
    __shared__ float sm[32][33];
    const int j = blockIdx.z;
    const int m0 = blockIdx.x * 32, n0 = blockIdx.y * 32;
    const int tid = threadIdx.x;
    const float* P = psi + (size_t)j * NN * NN;
    {
        int nl = tid >> 3, c4 = tid & 7;
        float4 v = *(const float4*)&P[(size_t)(n0 + nl) * NN + m0 + c4 * 4];
        sm[nl][c4 * 4 + 0] = v.x;
        sm[nl][c4 * 4 + 1] = v.y;
        sm[nl][c4 * 4 + 2] = v.z;
        sm[nl][c4 * 4 + 3] = v.w;
    }
    __syncthreads();
    {
        int ml = tid >> 3, p = tid & 7;
        float a0 = sm[4 * p + 0][ml], a1 = sm[4 * p + 1][ml];
        float a2 = sm[4 * p + 2][ml], a3 = sm[4 * p + 3][ml];
        float h0 = __half2float(__float2half_rn(a0));
        float h1 = __half2float(__float2half_rn(a1));
        float h2 = __half2float(__float2half_rn(a2));
        float h3 = __half2float(__float2half_rn(a3));
        size_t o = (size_t)j * NN * NW2 + (size_t)(m0 + ml) * NW2 + (n0 >> 1) + 2 * p;
        *(uint2*)&g_P2h[o] = make_uint2(pack2(a0, a1), pack2(a2, a3));
        *(uint2*)&g_P2l[o] = make_uint2(pack2(a0 - h0, a1 - h1), pack2(a2 - h2, a3 - h3));
    }
}

// ---------------- pack: sum split-K halves, abs, phi cols 1..4, S2 hi/lo ----
__global__ void pack_s1(const float* __restrict__ lp, float* __restrict__ out) {
    const int row = blockIdx.x, tid = threadIdx.x;     // 512 rows
    const float4* A = (const float4*)(g_S1f) + (size_t)row * (NN / 4);
    const float4* B = (const float4*)(g_S1f + 512 * NN) + (size_t)row * (NN / 4);
    const float4* L = (const float4*)lp;
    float s = 0.0f;
    uint32_t hw[4], lw[4];
    #pragma unroll
    for (int q = 0; q < 2; q++) {
        int i4 = tid * 2 + q;
        float4 a = A[i4], b = B[i4], l = L[i4];
        float v0 = fabsf(a.x + b.x), v1 = fabsf(a.y + b.y);
        float v2 = fabsf(a.z + b.z), v3 = fabsf(a.w + b.w);
        s += v0 * l.x + v1 * l.y + v2 * l.z + v3 * l.w;
        float h0 = __half2float(__float2half_rn(v0));
        float h1 = __half2float(__float2half_rn(v1));
        float h2 = __half2float(__float2half_rn(v2));
        float h3 = __half2float(__float2half_rn(v3));
        hw[q * 2 + 0] = pack2(v0, v1);
        hw[q * 2 + 1] = pack2(v2, v3);
        lw[q * 2 + 0] = pack2(v0 - h0, v1 - h1);
        lw[q * 2 + 1] = pack2(v2 - h2, v3 - h3);
    }
    *(uint4*)&g_S2h[(size_t)row * NW2 + tid * 4] = make_uint4(hw[0], hw[1], hw[2], hw[3]);
    *(uint4*)&g_S2l[(size_t)row * NW2 + tid * 4] = make_uint4(lw[0], lw[1], lw[2], lw[3]);
    __shared__ float red[8];
    #pragma unroll
    for (int o = 16; o; o >>= 1) s += __shfl_xor_sync(0xffffffffu, s, o);
    if ((tid & 31) == 0) red[tid >> 5] = s;
    __syncthreads();
    if (tid < 8) {
        s = red[tid];
        #pragma unroll
        for (int o = 4; o; o >>= 1) s += __shfl_xor_sync(0xffu, s, o);
        if (tid == 0) {
            int b = row >> 6, j = (row >> 4) & 3, f = row & 15;
            out[(b * FF + f) * NCOLS + 1 + j] = s;     // sole writer of cols 1..4
        }
    }
}

// ---------------- fused fp16 3-term tensor GEMM ----------------
// LAYER 1: split-K partial (blockIdx.y = k-half), raw fp32 C out. NI=4.
// LAYER 2: R10 config (NI=8, occ 2), fused abs+lowpass epilogue.
template <int LAYER, int NI>
__global__ __launch_bounds__(256, (NI <= 4 ? 3 : 2))
void gemm_f16(const float* __restrict__ lp, float* __restrict__ phi) {
    constexpr int TN  = NI * 16;
    constexpr int APL = 128 * 80;
    constexpr int BPL = TN * 80;
    constexpr int STB = 2 * APL + 2 * BPL;
    constexpr int NKC = (LAYER == 1) ? 32 : 64;        // k-chunks (split-K halves)

    extern __shared__ __align__(1024) char smc[];
    const uint32_t sb = smem_u32(smc);
    const int tid = threadIdx.x;
    const int lane = tid & 31, w = tid >> 5;
    const int wm = w & 3, wn = w >> 2;
    const int g = lane >> 2, t = lane & 3;
    const int j  = blockIdx.z;
    const int n0 = blockIdx.x * TN;
    const int ky = (LAYER == 1) ? blockIdx.y : 0;
    const int m0 = (LAYER == 1) ? 0 : blockIdx.y * 128;
    const int kw0 = ky * 512;                          // word offset of k-half

    const uint32_t* srcs[4] = {
        ((LAYER == 1) ? g_X2h : g_S2h) + (size_t)m0 * NW2 + kw0,
        ((LAYER == 1) ? g_X2l : g_S2l) + (size_t)m0 * NW2 + kw0,
        g_P2h + (size_t)j * NN * NW2 + (size_t)n0 * NW2 + kw0,
        g_P2l + (size_t)j * NN * NW2 + (size_t)n0 * NW2 + kw0 };

    const int lrow = lane & 7, lm = lane >> 3;
    uint32_t aoff[2];
    #pragma unroll
    for (int mi = 0; mi < 2; mi++)
        aoff[mi] = (uint32_t)((wm * 32 + mi * 16 + (lm & 1) * 8 + lrow) * 80
                              + (lm >> 1) * 16);
    const uint32_t boff = (uint32_t)((wn * NI * 8 + (lm >> 1) * 8 + lrow) * 80
                                     + (lm & 1) * 16);

    auto copy_stage = [&](int buf, int kc) {
        uint32_t st = sb + buf * STB;
        #pragma unroll
        for (int pl = 0; pl < 2; pl++) {
            uint32_t pb = st + pl * APL;
            const uint32_t* s = srcs[pl] + kc * 16;
            #pragma unroll
            for (int i = 0; i < 2; i++) {
                int cid = i * 256 + tid, row = cid >> 2, cc = cid & 3;
                cp16(pb + row * 80 + cc * 16, s + (size_t)row * NW2 + cc * 4);
            }
        }
        constexpr int BPC = (TN * 4) / 256;            // 1 (NI=4) / 2 (NI=8)
        #pragma unroll
        for (int pl = 0; pl < 2; pl++) {
            uint32_t pb = st + 2 * APL + pl * BPL;
            const uint32_t* s = srcs[2 + pl] + kc * 16;
            #pragma unroll
            for (int i = 0; i < BPC; i++) {
                int cid = i * 256 + tid, row = cid >> 2, cc = cid & 3;
                cp16(pb + row * 80 + cc * 16, s + (size_t)row * NW2 + cc * 4);
            }
        }
        asm volatile("cp.async.commit_group;\n");
    };

    float c[2][NI][4] = {};

    copy_stage(0, 0);
    for (int kt = 0; kt < NKC; kt++) {
        const int buf = kt & 1;
        if (kt + 1 < NKC) {
            copy_stage(buf ^ 1, kt + 1);
            asm volatile("cp.async.wait_group 1;\n");
        } else {
            asm volatile("cp.async.wait_group 0;\n");
        }
        __syncthreads();

        const uint32_t st = sb + buf * STB;
        #pragma unroll
        for (int kk = 0; kk < 2; kk++) {
            const uint32_t kb = kk * 32;
            uint32_t ah[2][4], al[2][4], bh[NI / 2][4];
            LDSM4(ah[0], st + aoff[0] + kb);
            LDSM4(ah[1], st + aoff[1] + kb);
            LDSM4(al[0], st + APL + aoff[0] + kb);
            LDSM4(al[1], st + APL + aoff[1] + kb);
            #pragma unroll
            for (int q = 0; q < NI / 2; q++)
                LDSM4(bh[q], st + 2 * APL + boff + q * 1280 + kb);

            #pragma unroll
            for (int ni = 0; ni < NI; ni++) {    // term 0: Al x Bh
                uint32_t b0 = bh[ni >> 1][(ni & 1) * 2], b1 = bh[ni >> 1][(ni & 1) * 2 + 1];
                MMA_F16(c[0][ni], al[0], b0, b1);
                MMA_F16(c[1][ni], al[1], b0, b1);
            }
            #pragma unroll
            for (int q = 0; q < NI / 2; q++) {   // term 1: Ah x Bl (streamed)
                uint32_t bl[4];
                LDSM4(bl, st + 2 * APL + BPL + boff + q * 1280 + kb);
                #pragma unroll
                for (int s = 0; s < 2; s++) {
                    MMA_F16(c[0][q * 2 + s], ah[0], bl[s * 2], bl[s * 2 + 1]);
                    MMA_F16(c[1][q * 2 + s], ah[1], bl[s * 2], bl[s * 2 + 1]);
                }
            }
            #pragma unroll
            for (int ni = 0; ni < NI; ni++) {    // term 2: Ah x Bh
                uint32_t b0 = bh[ni >> 1][(ni & 1) * 2], b1 = bh[ni >> 1][(ni & 1) * 2 + 1];
                MMA_F16(c[0][ni], ah[0], b0, b1);
                MMA_F16(c[1][ni], ah[1], b0, b1);
            }
        }
        __syncthreads();
    }

    if (LAYER == 1) {
        // raw fp32 partial C to g_S1f[ky]; rows remapped to S1 order
        float* dst = g_S1f + (size_t)ky * (512 * NN);
        #pragma unroll
        for (int mi = 0; mi < 2; mi++) {
            #pragma unroll
            for (int ni = 0; ni < NI; ni++) {
                const int m = n0 + wn * NI * 8 + ni * 8 + 2 * t;
                const int r0 = wm * 32 + mi * 16 + g, r1 = r0 + 8;
                int s0 = (((r0 >> 4) * JS + j) << 4) + (r0 & 15);
                int s1 = (((r1 >> 4) * JS + j) << 4) + (r1 & 15);
                *(float2*)&dst[(size_t)s0 * NN + m] = make_float2(c[mi][ni][0], c[mi][ni][1]);
                *(float2*)&dst[(size_t)s1 * NN + m] = make_float2(c[mi][ni][2], c[mi][ni][3]);
            }
        }
    } else {
        float p[2][2] = {};
        #pragma unroll
        for (int mi = 0; mi < 2; mi++) {
            #pragma unroll
            for (int ni = 0; ni < NI; ni++) {
                const int m = n0 + wn * NI * 8 + ni * 8 + 2 * t;
                float v0 = fabsf(c[mi][ni][0]), v1 = fabsf(c[mi][ni][1]);
                float v2 = fabsf(c[mi][ni][2]), v3 = fabsf(c[mi][ni][3]);
                float l0 = __ldg(&lp[m]), l1 = __ldg(&lp[m + 1]);
                p[mi][0] += v0 * l0 + v1 * l1;
                p[mi][1] += v2 * l0 + v3 * l1;
            }
        }
        #pragma unroll
        for (int mi = 0; mi < 2; mi++) {
            #pragma unroll
            for (int s = 0; s < 2; s++) {
                float v = p[mi][s];
                v += __shfl_xor_sync(0xffffffffu, v, 1);
                v += __shfl_xor_sync(0xffffffffu, v, 2);
                if (t == 0) {
                    const int r = m0 + wm * 32 + mi * 16 + g + s * 8;
                    int b = r >> 6, j1 = (r >> 4) & 3, f = r & 15;
                    atomicAdd(&phi[(b * FF + f) * NCOLS + 5 + j1 * 4 + j], v);
                }
            }
        }
    }
}

// ---------------- launch ----------------
extern "C" void kernel_launch(void* const* d_in, const int* in_sizes, int n_in,
                              void* d_out, int out_size) {
    const float* x   = (const float*)d_in[0];   // (8,16,2048)
    const float* psi = (const float*)d_in[1];   // (4,2048,2048)
    const float* lp  = (const float*)d_in[2];   // (2048,)
    float* out = (float*)d_out;                 // (8,16,21)
    (void)in_sizes; (void)n_in; (void)out_size;

    constexpr int SM1 = 2 * (2 * 128 * 80 + 2 * 64 * 80);    // 61440 (NI=4)
    constexpr int SM2 = 2 * (2 * 128 * 80 + 2 * 128 * 80);   // 81920 (NI=8)
    cudaFuncSetAttribute(gemm_f16<1, 4>, cudaFuncAttributeMaxDynamicSharedMemorySize, SM1);
    cudaFuncSetAttribute(gemm_f16<2, 8>, cudaFuncAttributeMaxDynamicSharedMemorySize, SM2);

    prep_kernel<<<BB * FF, 256>>>(x, lp, out);
    transpose_pack_psi<<<dim3(64, 64, JS), 256>>>(psi);
    // layer 1 split-K: 32 N-tiles x 2 k-halves x 4 j = 256 CTAs
    gemm_f16<1, 4><<<dim3(32, 2, 4), 256, SM1>>>(lp, out);
    pack_s1<<<512, 256>>>(lp, out);                          // sum halves, phi 1..4, S2 pack
    // layer 2: R10 config — 16 N-tiles x 4 M-tiles x 4 j
    gemm_f16<2, 8><<<dim3(16, 4, 4), 256, SM2>>>(lp, out);
}

// round 15
// speedup vs baseline: 1.1048x; 1.0009x over previous
#include <cuda_runtime.h>
#include <cuda_fp16.h>
#include <math.h>
#include <stdint.h>

// Problem constants
#define BB 8
#define FF 16
#define NN 2048
#define JS 4
#define NCOLS 21
#define OUT_ELEMS (BB*FF*NCOLS)
#define NW2 1024                 // packed fp16-pair words per row

// ---------------- scratch ----------------
__device__ __align__(256) uint32_t g_X2h[BB*FF*NW2], g_X2l[BB*FF*NW2];
__device__ __align__(256) uint32_t g_P2h[(size_t)JS*NN*NW2];
__device__ __align__(256) uint32_t g_P2l[(size_t)JS*NN*NW2];
__device__ __align__(256) uint32_t g_S2h[(size_t)BB*JS*FF*NW2];
__device__ __align__(256) uint32_t g_S2l[(size_t)BB*JS*FF*NW2];
__device__ __align__(256) float    g_S1f[2 * 512 * NN];     // split-K partials (8 MB)

// ---------------- helpers ----------------
__device__ __forceinline__ uint32_t smem_u32(const void* p) {
    uint32_t a;
    asm("{ .reg .u64 t; cvta.to.shared.u64 t, %1; cvt.u32.u64 %0, t; }" : "=r"(a) : "l"(p));
    return a;
}
__device__ __forceinline__ void cp16(uint32_t s, const void* g) {
    asm volatile("cp.async.cg.shared.global [%0], [%1], 16;\n" :: "r"(s), "l"(g));
}
__device__ __forceinline__ uint32_t pack2(float a, float b) {
    __half2 h = __floats2half2_rn(a, b);
    return *reinterpret_cast<uint32_t*>(&h);
}
#define MMA_F16(C, A, B0, B1)                                                 \
    asm volatile(                                                             \
        "mma.sync.aligned.m16n8k16.row.col.f32.f16.f16.f32 "                  \
        "{%0,%1,%2,%3}, {%4,%5,%6,%7}, {%8,%9}, {%0,%1,%2,%3};\n"             \
        : "+f"((C)[0]), "+f"((C)[1]), "+f"((C)[2]), "+f"((C)[3])              \
        : "r"((A)[0]), "r"((A)[1]), "r"((A)[2]), "r"((A)[3]), "r"(B0), "r"(B1))
#define LDSM4(R, addr)                                                        \
    asm volatile("ldmatrix.sync.aligned.m8n8.x4.shared.b16 {%0,%1,%2,%3}, [%4];" \
        : "=r"((R)[0]), "=r"((R)[1]), "=r"((R)[2]), "=r"((R)[3]) : "r"(addr))

// ---------------- fused prep: phi0 + phi-zero + x hi/lo split ----------------
__global__ void prep_kernel(const float* __restrict__ x, const float* __restrict__ lp,
                            float* __restrict__ out) {
    const int r = blockIdx.x, tid = threadIdx.x;
    const float2* x2 = (const float2*)(x) + (size_t)r * NW2;
    const float2* lp2 = (const float2*)lp;
    float s = 0.0f;
    #pragma unroll
    for (int it = 0; it < 4; it++) {
        int wd = it * 256 + tid;
        float2 v = x2[wd];
        float2 l = lp2[wd];
        s += v.x * l.x + v.y * l.y;
        float ah = __half2float(__float2half_rn(v.x));
        float bh = __half2float(__float2half_rn(v.y));
        g_X2h[r * NW2 + wd] = pack2(v.x, v.y);
        g_X2l[r * NW2 + wd] = pack2(v.x - ah, v.y - bh);
    }
    if (tid >= 5 && tid < NCOLS) out[r * NCOLS + tid] = 0.0f;  // zero cols 5..20
    __shared__ float red[8];
    #pragma unroll
    for (int o = 16; o; o >>= 1) s += __shfl_xor_sync(0xffffffffu, s, o);
    if ((tid & 31) == 0) red[tid >> 5] = s;
    __syncthreads();
    if (tid < 8) {
        s = red[tid];
        #pragma unroll
        for (int o = 4; o; o >>= 1) s += __shfl_xor_sync(0xffu, s, o);
        if (tid == 0) out[r * NCOLS + 0] = s;
    }
}

// ---------------- psi transpose+split (R10 wide-IO version) ----------------
__global__ void transpose_pack_psi(const float* __restrict__ psi) {
    __shared__ float sm[32][33];
    const int j = blockIdx.z;
    const int m0 = blockIdx.x * 32, n0 = blockIdx.y * 32;
    const int tid = threadIdx.x;
    const float* P = psi + (size_t)j * NN * NN;
    {
        int nl = tid >> 3, c4 = tid & 7;
        float4 v = *(const float4*)&P[(size_t)(n0 + nl) * NN + m0 + c4 * 4];
        sm[nl][c4 * 4 + 0] = v.x;
        sm[nl][c4 * 4 + 1] = v.y;
        sm[nl][c4 * 4 + 2] = v.z;
        sm[nl][c4 * 4 + 3] = v.w;
    }
    __syncthreads();
    {
        int ml = tid >> 3, p = tid & 7;
        float a0 = sm[4 * p + 0][ml], a1 = sm[4 * p + 1][ml];
        float a2 = sm[4 * p + 2][ml], a3 = sm[4 * p + 3][ml];
        float h0 = __half2float(__float2half_rn(a0));
        float h1 = __half2float(__float2half_rn(a1));
        float h2 = __half2float(__float2half_rn(a2));
        float h3 = __half2float(__float2half_rn(a3));
        size_t o = (size_t)j * NN * NW2 + (size_t)(m0 + ml) * NW2 + (n0 >> 1) + 2 * p;
        *(uint2*)&g_P2h[o] = make_uint2(pack2(a0, a1), pack2(a2, a3));
        *(uint2*)&g_P2l[o] = make_uint2(pack2(a0 - h0, a1 - h1), pack2(a2 - h2, a3 - h3));
    }
}

// ---------------- pack: sum split-K halves, abs, phi cols 1..4, S2 hi/lo ----
__global__ void pack_s1(const float* __restrict__ lp, float* __restrict__ out) {
    const int row = blockIdx.x, tid = threadIdx.x;     // 512 rows
    const float4* A = (const float4*)(g_S1f) + (size_t)row * (NN / 4);
    const float4* B = (const float4*)(g_S1f + 512 * NN) + (size_t)row * (NN / 4);
    const float4* L = (const float4*)lp;
    float s = 0.0f;
    uint32_t hw[4], lw[4];
    #pragma unroll
    for (int q = 0; q < 2; q++) {
        int i4 = tid * 2 + q;
        float4 a = A[i4], b = B[i4], l = L[i4];
        float v0 = fabsf(a.x + b.x), v1 = fabsf(a.y + b.y);
        float v2 = fabsf(a.z + b.z), v3 = fabsf(a.w + b.w);
        s += v0 * l.x + v1 * l.y + v2 * l.z + v3 * l.w;
        float h0 = __half2float(__float2half_rn(v0));
        float h1 = __half2float(__float2half_rn(v1));
        float h2 = __half2float(__float2half_rn(v2));
        float h3 = __half2float(__float2half_rn(v3));
        hw[q * 2 + 0] = pack2(v0, v1);
        hw[q * 2 + 1] = pack2(v2, v3);
        lw[q * 2 + 0] = pack2(v0 - h0, v1 - h1);
        lw[q * 2 + 1] = pack2(v2 - h2, v3 - h3);
    }
    *(uint4*)&g_S2h[(size_t)row * NW2 + tid * 4] = make_uint4(hw[0], hw[1], hw[2], hw[3]);
    *(uint4*)&g_S2l[(size_t)row * NW2 + tid * 4] = make_uint4(lw[0], lw[1], lw[2], lw[3]);
    __shared__ float red[8];
    #pragma unroll
    for (int o = 16; o; o >>= 1) s += __shfl_xor_sync(0xffffffffu, s, o);
    if ((tid & 31) == 0) red[tid >> 5] = s;
    __syncthreads();
    if (tid < 8) {
        s = red[tid];
        #pragma unroll
        for (int o = 4; o; o >>= 1) s += __shfl_xor_sync(0xffu, s, o);
        if (tid == 0) {
            int b = row >> 6, j = (row >> 4) & 3, f = row & 15;
            out[(b * FF + f) * NCOLS + 1 + j] = s;
        }
    }
}

// ---------------- fused fp16 3-term tensor GEMM ----------------
// R15: single barrier per chunk. Loop: wait_group 0 -> barrier -> issue
// copy(kt+1) -> compute(kt). Barrier release implies all warps finished
// compute(kt-1), so overwriting that buffer post-barrier is race-free; warps
// destagger across copy+compute, keeping the HMMA pipe fed.
template <int LAYER, int NI>
__global__ __launch_bounds__(256, (NI <= 4 ? 3 : 2))
void gemm_f16(const float* __restrict__ lp, float* __restrict__ phi) {
    constexpr int TN  = NI * 16;
    constexpr int APL = 128 * 80;
    constexpr int BPL = TN * 80;
    constexpr int STB = 2 * APL + 2 * BPL;
    constexpr int NKC = (LAYER == 1) ? 32 : 64;

    extern __shared__ __align__(1024) char smc[];
    const uint32_t sb = smem_u32(smc);
    const int tid = threadIdx.x;
    const int lane = tid & 31, w = tid >> 5;
    const int wm = w & 3, wn = w >> 2;
    const int g = lane >> 2, t = lane & 3;
    const int j  = blockIdx.z;
    const int n0 = blockIdx.x * TN;
    const int ky = (LAYER == 1) ? blockIdx.y : 0;
    const int m0 = (LAYER == 1) ? 0 : blockIdx.y * 128;
    const int kw0 = ky * 512;

    const uint32_t* srcs[4] = {
        ((LAYER == 1) ? g_X2h : g_S2h) + (size_t)m0 * NW2 + kw0,
        ((LAYER == 1) ? g_X2l : g_S2l) + (size_t)m0 * NW2 + kw0,
        g_P2h + (size_t)j * NN * NW2 + (size_t)n0 * NW2 + kw0,
        g_P2l + (size_t)j * NN * NW2 + (size_t)n0 * NW2 + kw0 };

    const int lrow = lane & 7, lm = lane >> 3;
    uint32_t aoff[2];
    #pragma unroll
    for (int mi = 0; mi < 2; mi++)
        aoff[mi] = (uint32_t)((wm * 32 + mi * 16 + (lm & 1) * 8 + lrow) * 80
                              + (lm >> 1) * 16);
    const uint32_t boff = (uint32_t)((wn * NI * 8 + (lm >> 1) * 8 + lrow) * 80
                                     + (lm & 1) * 16);

    auto copy_stage = [&](int buf, int kc) {
        uint32_t st = sb + buf * STB;
        #pragma unroll
        for (int pl = 0; pl < 2; pl++) {
            uint32_t pb = st + pl * APL;
            const uint32_t* s = srcs[pl] + kc * 16;
            #pragma unroll
            for (int i = 0; i < 2; i++) {
                int cid = i * 256 + tid, row = cid >> 2, cc = cid & 3;
                cp16(pb + row * 80 + cc * 16, s + (size_t)row * NW2 + cc * 4);
            }
        }
        constexpr int BPC = (TN * 4) / 256;
        #pragma unroll
        for (int pl = 0; pl < 2; pl++) {
            uint32_t pb = st + 2 * APL + pl * BPL;
            const uint32_t* s = srcs[2 + pl] + kc * 16;
            #pragma unroll
            for (int i = 0; i < BPC; i++) {
                int cid = i * 256 + tid, row = cid >> 2, cc = cid & 3;
                cp16(pb + row * 80 + cc * 16, s + (size_t)row * NW2 + cc * 4);
            }
        }
        asm volatile("cp.async.commit_group;\n");
    };

    float c[2][NI][4] = {};

    copy_stage(0, 0);
    for (int kt = 0; kt < NKC; kt++) {
        const int buf = kt & 1;
        asm volatile("cp.async.wait_group 0;\n");   // own share of stage kt done
        __syncthreads();                            // all shares done; prev compute done
        if (kt + 1 < NKC) copy_stage(buf ^ 1, kt + 1);   // async fill of other buffer

        const uint32_t st = sb + buf * STB;
        #pragma unroll
        for (int kk = 0; kk < 2; kk++) {
            const uint32_t kb = kk * 32;
            uint32_t ah[2][4], al[2][4], bh[NI / 2][4];
            LDSM4(ah[0], st + aoff[0] + kb);
            LDSM4(ah[1], st + aoff[1] + kb);
            LDSM4(al[0], st + APL + aoff[0] + kb);
            LDSM4(al[1], st + APL + aoff[1] + kb);
            #pragma unroll
            for (int q = 0; q < NI / 2; q++)
                LDSM4(bh[q], st + 2 * APL + boff + q * 1280 + kb);

            #pragma unroll
            for (int ni = 0; ni < NI; ni++) {    // term 0: Al x Bh
                uint32_t b0 = bh[ni >> 1][(ni & 1) * 2], b1 = bh[ni >> 1][(ni & 1) * 2 + 1];
                MMA_F16(c[0][ni], al[0], b0, b1);
                MMA_F16(c[1][ni], al[1], b0, b1);
            }
            #pragma unroll
            for (int q = 0; q < NI / 2; q++) {   // term 1: Ah x Bl (streamed)
                uint32_t bl[4];
                LDSM4(bl, st + 2 * APL + BPL + boff + q * 1280 + kb);
                #pragma unroll
                for (int s = 0; s < 2; s++) {
                    MMA_F16(c[0][q * 2 + s], ah[0], bl[s * 2], bl[s * 2 + 1]);
                    MMA_F16(c[1][q * 2 + s], ah[1], bl[s * 2], bl[s * 2 + 1]);
                }
            }
            #pragma unroll
            for (int ni = 0; ni < NI; ni++) {    // term 2: Ah x Bh
                uint32_t b0 = bh[ni >> 1][(ni & 1) * 2], b1 = bh[ni >> 1][(ni & 1) * 2 + 1];
                MMA_F16(c[0][ni], ah[0], b0, b1);
                MMA_F16(c[1][ni], ah[1], b0, b1);
            }
        }
    }

    if (LAYER == 1) {
        float* dst = g_S1f + (size_t)ky * (512 * NN);
        #pragma unroll
        for (int mi = 0; mi < 2; mi++) {
            #pragma unroll
            for (int ni = 0; ni < NI; ni++) {
                const int m = n0 + wn * NI * 8 + ni * 8 + 2 * t;
                const int r0 = wm * 32 + mi * 16 + g, r1 = r0 + 8;
                int s0 = (((r0 >> 4) * JS + j) << 4) + (r0 & 15);
                int s1 = (((r1 >> 4) * JS + j) << 4) + (r1 & 15);
                *(float2*)&dst[(size_t)s0 * NN + m] = make_float2(c[mi][ni][0], c[mi][ni][1]);
                *(float2*)&dst[(size_t)s1 * NN + m] = make_float2(c[mi][ni][2], c[mi][ni][3]);
            }
        }
    } else {
        float p[2][2] = {};
        #pragma unroll
        for (int mi = 0; mi < 2; mi++) {
            #pragma unroll
            for (int ni = 0; ni < NI; ni++) {
                const int m = n0 + wn * NI * 8 + ni * 8 + 2 * t;
                float v0 = fabsf(c[mi][ni][0]), v1 = fabsf(c[mi][ni][1]);
                float v2 = fabsf(c[mi][ni][2]), v3 = fabsf(c[mi][ni][3]);
                float l0 = __ldg(&lp[m]), l1 = __ldg(&lp[m + 1]);
                p[mi][0] += v0 * l0 + v1 * l1;
                p[mi][1] += v2 * l0 + v3 * l1;
            }
        }
        #pragma unroll
        for (int mi = 0; mi < 2; mi++) {
            #pragma unroll
            for (int s = 0; s < 2; s++) {
                float v = p[mi][s];
                v += __shfl_xor_sync(0xffffffffu, v, 1);
                v += __shfl_xor_sync(0xffffffffu, v, 2);
                if (t == 0) {
                    const int r = m0 + wm * 32 + mi * 16 + g + s * 8;
                    int b = r >> 6, j1 = (r >> 4) & 3, f = r & 15;
                    atomicAdd(&phi[(b * FF + f) * NCOLS + 5 + j1 * 4 + j], v);
                }
            }
        }
    }
}

// ---------------- launch ----------------
extern "C" void kernel_launch(void* const* d_in, const int* in_sizes, int n_in,
                              void* d_out, int out_size) {
    const float* x   = (const float*)d_in[0];   // (8,16,2048)
    const float* psi = (const float*)d_in[1];   // (4,2048,2048)
    const float* lp  = (const float*)d_in[2];   // (2048,)
    float* out = (float*)d_out;                 // (8,16,21)
    (void)in_sizes; (void)n_in; (void)out_size;

    constexpr int SM1 = 2 * (2 * 128 * 80 + 2 * 64 * 80);    // 61440 (NI=4)
    constexpr int SM2 = 2 * (2 * 128 * 80 + 2 * 128 * 80);   // 81920 (NI=8)
    cudaFuncSetAttribute(gemm_f16<1, 4>, cudaFuncAttributeMaxDynamicSharedMemorySize, SM1);
    cudaFuncSetAttribute(gemm_f16<2, 8>, cudaFuncAttributeMaxDynamicSharedMemorySize, SM2);

    prep_kernel<<<BB * FF, 256>>>(x, lp, out);
    transpose_pack_psi<<<dim3(64, 64, JS), 256>>>(psi);
    // layer 1 split-K: 32 N-tiles x 2 k-halves x 4 j = 256 CTAs
    gemm_f16<1, 4><<<dim3(32, 2, 4), 256, SM1>>>(lp, out);
    pack_s1<<<512, 256>>>(lp, out);
    // layer 2: 16 N-tiles x 4 M-tiles x 4 j = 256 CTAs
    gemm_f16<2, 8><<<dim3(16, 4, 4), 256, SM2>>>(lp, out);
}

// round 17
// speedup vs baseline: 1.1138x; 1.0081x over previous
#include <cuda_runtime.h>
#include <cuda_fp16.h>
#include <math.h>
#include <stdint.h>

// Problem constants
#define BB 8
#define FF 16
#define NN 2048
#define JS 4
#define NCOLS 21
#define OUT_ELEMS (BB*FF*NCOLS)
#define NW2 1024                 // packed fp16-pair words per row

// ---------------- scratch ----------------
__device__ __align__(256) uint32_t g_X2h[BB*FF*NW2], g_X2l[BB*FF*NW2];
__device__ __align__(256) uint32_t g_P2h[(size_t)JS*NN*NW2];
__device__ __align__(256) uint32_t g_P2l[(size_t)JS*NN*NW2];
__device__ __align__(256) uint32_t g_S2h[(size_t)BB*JS*FF*NW2];
__device__ __align__(256) uint32_t g_S2l[(size_t)BB*JS*FF*NW2];
__device__ __align__(256) float    g_S1f[2 * 512 * NN];     // split-K partials (8 MB)

// ---------------- helpers ----------------
__device__ __forceinline__ uint32_t smem_u32(const void* p) {
    uint32_t a;
    asm("{ .reg .u64 t; cvta.to.shared.u64 t, %1; cvt.u32.u64 %0, t; }" : "=r"(a) : "l"(p));
    return a;
}
__device__ __forceinline__ void cp16(uint32_t s, const void* g) {
    asm volatile("cp.async.cg.shared.global [%0], [%1], 16;\n" :: "r"(s), "l"(g));
}
__device__ __forceinline__ uint32_t pack2(float a, float b) {
    __half2 h = __floats2half2_rn(a, b);
    return *reinterpret_cast<uint32_t*>(&h);
}
#define MMA_F16(C, A, B0, B1)                                                 \
    asm volatile(                                                             \
        "mma.sync.aligned.m16n8k16.row.col.f32.f16.f16.f32 "                  \
        "{%0,%1,%2,%3}, {%4,%5,%6,%7}, {%8,%9}, {%0,%1,%2,%3};\n"             \
        : "+f"((C)[0]), "+f"((C)[1]), "+f"((C)[2]), "+f"((C)[3])              \
        : "r"((A)[0]), "r"((A)[1]), "r"((A)[2]), "r"((A)[3]), "r"(B0), "r"(B1))
#define LDSM4(R, addr)                                                        \
    asm volatile("ldmatrix.sync.aligned.m8n8.x4.shared.b16 {%0,%1,%2,%3}, [%4];" \
        : "=r"((R)[0]), "=r"((R)[1]), "=r"((R)[2]), "=r"((R)[3]) : "r"(addr))

// ---------------- fused prep: phi0 + phi-zero + x hi/lo split ----------------
__global__ void prep_kernel(const float* __restrict__ x, const float* __restrict__ lp,
                            float* __restrict__ out) {
    const int r = blockIdx.x, tid = threadIdx.x;
    const float2* x2 = (const float2*)(x) + (size_t)r * NW2;
    const float2* lp2 = (const float2*)lp;
    float s = 0.0f;
    #pragma unroll
    for (int it = 0; it < 4; it++) {
        int wd = it * 256 + tid;
        float2 v = x2[wd];
        float2 l = lp2[wd];
        s += v.x * l.x + v.y * l.y;
        float ah = __half2float(__float2half_rn(v.x));
        float bh = __half2float(__float2half_rn(v.y));
        g_X2h[r * NW2 + wd] = pack2(v.x, v.y);
        g_X2l[r * NW2 + wd] = pack2(v.x - ah, v.y - bh);
    }
    if (tid >= 5 && tid < NCOLS) out[r * NCOLS + tid] = 0.0f;  // zero cols 5..20
    __shared__ float red[8];
    #pragma unroll
    for (int o = 16; o; o >>= 1) s += __shfl_xor_sync(0xffffffffu, s, o);
    if ((tid & 31) == 0) red[tid >> 5] = s;
    __syncthreads();
    if (tid < 8) {
        s = red[tid];
        #pragma unroll
        for (int o = 4; o; o >>= 1) s += __shfl_xor_sync(0xffu, s, o);
        if (tid == 0) out[r * NCOLS + 0] = s;
    }
}

// ---------------- psi transpose+split, R16 instruction-diet edition ---------
// 64(n) x 64(m) tiles, grid (32 m-tiles, 32 n-tiles, 4). 256 threads.
// smem stride 68 words: float4 STS aligned (272 B rows); read phase
// addr=(seg*16+q)*68+ml -> consecutive ml = consecutive banks (conflict-free).
__global__ void transpose_pack_psi(const float* __restrict__ psi) {
    __shared__ float sm[64][68];
    const int j = blockIdx.z;
    const int m0 = blockIdx.x * 64, n0 = blockIdx.y * 64;
    const int tid = threadIdx.x;
    const float* P = psi + (size_t)j * NN * NN;

    // load 64 n-rows x 64 m-cols, float4 (4 per thread)
    {
        const int row16 = tid >> 4, c4 = tid & 15;
        #pragma unroll
        for (int i = 0; i < 4; i++) {
            int nl = row16 + i * 16;
            float4 v = *(const float4*)&P[(size_t)(n0 + nl) * NN + m0 + c4 * 4];
            *(float4*)&sm[nl][c4 * 4] = v;
        }
    }
    __syncthreads();

    // write: warp = 32 consecutive m-rows, one 16-n segment (seg = tid>>6)
    {
        const int ml = tid & 63, seg = tid >> 6;
        float vv[16];
        #pragma unroll
        for (int q = 0; q < 16; q++) vv[q] = sm[seg * 16 + q][ml];
        uint32_t hw[8], lw[8];
        #pragma unroll
        for (int q = 0; q < 8; q++) {
            float a = vv[2 * q], b = vv[2 * q + 1];
            __half2 hp = __floats2half2_rn(a, b);
            hw[q] = *(uint32_t*)&hp;
            float2 hf = __half22float2(hp);
            __half2 lp2v = __floats2half2_rn(a - hf.x, b - hf.y);
            lw[q] = *(uint32_t*)&lp2v;
        }
        size_t o = (size_t)j * NN * NW2 + (size_t)(m0 + ml) * NW2 + (n0 >> 1) + seg * 8;
        *(uint4*)&g_P2h[o]     = make_uint4(hw[0], hw[1], hw[2], hw[3]);
        *(uint4*)&g_P2h[o + 4] = make_uint4(hw[4], hw[5], hw[6], hw[7]);
        *(uint4*)&g_P2l[o]     = make_uint4(lw[0], lw[1], lw[2], lw[3]);
        *(uint4*)&g_P2l[o + 4] = make_uint4(lw[4], lw[5], lw[6], lw[7]);
    }
}

// ---------------- pack: sum split-K halves, abs, phi cols 1..4, S2 hi/lo ----
__global__ void pack_s1(const float* __restrict__ lp, float* __restrict__ out) {
    const int row = blockIdx.x, tid = threadIdx.x;     // 512 rows
    const float4* A = (const float4*)(g_S1f) + (size_t)row * (NN / 4);
    const float4* B = (const float4*)(g_S1f + 512 * NN) + (size_t)row * (NN / 4);
    const float4* L = (const float4*)lp;
    float s = 0.0f;
    uint32_t hw[4], lw[4];
    #pragma unroll
    for (int q = 0; q < 2; q++) {
        int i4 = tid * 2 + q;
        float4 a = A[i4], b = B[i4], l = L[i4];
        float v0 = fabsf(a.x + b.x), v1 = fabsf(a.y + b.y);
        float v2 = fabsf(a.z + b.z), v3 = fabsf(a.w + b.w);
        s += v0 * l.x + v1 * l.y + v2 * l.z + v3 * l.w;
        float h0 = __half2float(__float2half_rn(v0));
        float h1 = __half2float(__float2half_rn(v1));
        float h2 = __half2float(__float2half_rn(v2));
        float h3 = __half2float(__float2half_rn(v3));
        hw[q * 2 + 0] = pack2(v0, v1);
        hw[q * 2 + 1] = pack2(v2, v3);
        lw[q * 2 + 0] = pack2(v0 - h0, v1 - h1);
        lw[q * 2 + 1] = pack2(v2 - h2, v3 - h3);
    }
    *(uint4*)&g_S2h[(size_t)row * NW2 + tid * 4] = make_uint4(hw[0], hw[1], hw[2], hw[3]);
    *(uint4*)&g_S2l[(size_t)row * NW2 + tid * 4] = make_uint4(lw[0], lw[1], lw[2], lw[3]);
    __shared__ float red[8];
    #pragma unroll
    for (int o = 16; o; o >>= 1) s += __shfl_xor_sync(0xffffffffu, s, o);
    if ((tid & 31) == 0) red[tid >> 5] = s;
    __syncthreads();
    if (tid < 8) {
        s = red[tid];
        #pragma unroll
        for (int o = 4; o; o >>= 1) s += __shfl_xor_sync(0xffu, s, o);
        if (tid == 0) {
            int b = row >> 6, j = (row >> 4) & 3, f = row & 15;
            out[(b * FF + f) * NCOLS + 1 + j] = s;
        }
    }
}

// ---------------- fused fp16 3-term tensor GEMM (R15, frozen) ---------------
template <int LAYER, int NI>
__global__ __launch_bounds__(256, (NI <= 4 ? 3 : 2))
void gemm_f16(const float* __restrict__ lp, float* __restrict__ phi) {
    constexpr int TN  = NI * 16;
    constexpr int APL = 128 * 80;
    constexpr int BPL = TN * 80;
    constexpr int STB = 2 * APL + 2 * BPL;
    constexpr int NKC = (LAYER == 1) ? 32 : 64;

    extern __shared__ __align__(1024) char smc[];
    const uint32_t sb = smem_u32(smc);
    const int tid = threadIdx.x;
    const int lane = tid & 31, w = tid >> 5;
    const int wm = w & 3, wn = w >> 2;
    const int g = lane >> 2, t = lane & 3;
    const int j  = blockIdx.z;
    const int n0 = blockIdx.x * TN;
    const int ky = (LAYER == 1) ? blockIdx.y : 0;
    const int m0 = (LAYER == 1) ? 0 : blockIdx.y * 128;
    const int kw0 = ky * 512;

    const uint32_t* srcs[4] = {
        ((LAYER == 1) ? g_X2h : g_S2h) + (size_t)m0 * NW2 + kw0,
        ((LAYER == 1) ? g_X2l : g_S2l) + (size_t)m0 * NW2 + kw0,
        g_P2h + (size_t)j * NN * NW2 + (size_t)n0 * NW2 + kw0,
        g_P2l + (size_t)j * NN * NW2 + (size_t)n0 * NW2 + kw0 };

    const int lrow = lane & 7, lm = lane >> 3;
    uint32_t aoff[2];
    #pragma unroll
    for (int mi = 0; mi < 2; mi++)
        aoff[mi] = (uint32_t)((wm * 32 + mi * 16 + (lm & 1) * 8 + lrow) * 80
                              + (lm >> 1) * 16);
    const uint32_t boff = (uint32_t)((wn * NI * 8 + (lm >> 1) * 8 + lrow) * 80
                                     + (lm & 1) * 16);

    auto copy_stage = [&](int buf, int kc) {
        uint32_t st = sb + buf * STB;
        #pragma unroll
        for (int pl = 0; pl < 2; pl++) {
            uint32_t pb = st + pl * APL;
            const uint32_t* s = srcs[pl] + kc * 16;
            #pragma unroll
            for (int i = 0; i < 2; i++) {
                int cid = i * 256 + tid, row = cid >> 2, cc = cid & 3;
                cp16(pb + row * 80 + cc * 16, s + (size_t)row * NW2 + cc * 4);
            }
        }
        constexpr int BPC = (TN * 4) / 256;
        #pragma unroll
        for (int pl = 0; pl < 2; pl++) {
            uint32_t pb = st + 2 * APL + pl * BPL;
            const uint32_t* s = srcs[2 + pl] + kc * 16;
            #pragma unroll
            for (int i = 0; i < BPC; i++) {
                int cid = i * 256 + tid, row = cid >> 2, cc = cid & 3;
                cp16(pb + row * 80 + cc * 16, s + (size_t)row * NW2 + cc * 4);
            }
        }
        asm volatile("cp.async.commit_group;\n");
    };

    float c[2][NI][4] = {};

    copy_stage(0, 0);
    for (int kt = 0; kt < NKC; kt++) {
        const int buf = kt & 1;
        asm volatile("cp.async.wait_group 0;\n");
        __syncthreads();
        if (kt + 1 < NKC) copy_stage(buf ^ 1, kt + 1);

        const uint32_t st = sb + buf * STB;
        #pragma unroll
        for (int kk = 0; kk < 2; kk++) {
            const uint32_t kb = kk * 32;
            uint32_t ah[2][4], al[2][4], bh[NI / 2][4];
            LDSM4(ah[0], st + aoff[0] + kb);
            LDSM4(ah[1], st + aoff[1] + kb);
            LDSM4(al[0], st + APL + aoff[0] + kb);
            LDSM4(al[1], st + APL + aoff[1] + kb);
            #pragma unroll
            for (int q = 0; q < NI / 2; q++)
                LDSM4(bh[q], st + 2 * APL + boff + q * 1280 + kb);

            #pragma unroll
            for (int ni = 0; ni < NI; ni++) {    // term 0: Al x Bh
                uint32_t b0 = bh[ni >> 1][(ni & 1) * 2], b1 = bh[ni >> 1][(ni & 1) * 2 + 1];
                MMA_F16(c[0][ni], al[0], b0, b1);
                MMA_F16(c[1][ni], al[1], b0, b1);
            }
            #pragma unroll
            for (int q = 0; q < NI / 2; q++) {   // term 1: Ah x Bl (streamed)
                uint32_t bl[4];
                LDSM4(bl, st + 2 * APL + BPL + boff + q * 1280 + kb);
                #pragma unroll
                for (int s = 0; s < 2; s++) {
                    MMA_F16(c[0][q * 2 + s], ah[0], bl[s * 2], bl[s * 2 + 1]);
                    MMA_F16(c[1][q * 2 + s], ah[1], bl[s * 2], bl[s * 2 + 1]);
                }
            }
            #pragma unroll
            for (int ni = 0; ni < NI; ni++) {    // term 2: Ah x Bh
                uint32_t b0 = bh[ni >> 1][(ni & 1) * 2], b1 = bh[ni >> 1][(ni & 1) * 2 + 1];
                MMA_F16(c[0][ni], ah[0], b0, b1);
                MMA_F16(c[1][ni], ah[1], b0, b1);
            }
        }
    }

    if (LAYER == 1) {
        float* dst = g_S1f + (size_t)ky * (512 * NN);
        #pragma unroll
        for (int mi = 0; mi < 2; mi++) {
            #pragma unroll
            for (int ni = 0; ni < NI; ni++) {
                const int m = n0 + wn * NI * 8 + ni * 8 + 2 * t;
                const int r0 = wm * 32 + mi * 16 + g, r1 = r0 + 8;
                int s0 = (((r0 >> 4) * JS + j) << 4) + (r0 & 15);
                int s1 = (((r1 >> 4) * JS + j) << 4) + (r1 & 15);
                *(float2*)&dst[(size_t)s0 * NN + m] = make_float2(c[mi][ni][0], c[mi][ni][1]);
                *(float2*)&dst[(size_t)s1 * NN + m] = make_float2(c[mi][ni][2], c[mi][ni][3]);
            }
        }
    } else {
        float p[2][2] = {};
        #pragma unroll
        for (int mi = 0; mi < 2; mi++) {
            #pragma unroll
            for (int ni = 0; ni < NI; ni++) {
                const int m = n0 + wn * NI * 8 + ni * 8 + 2 * t;
                float v0 = fabsf(c[mi][ni][0]), v1 = fabsf(c[mi][ni][1]);
                float v2 = fabsf(c[mi][ni][2]), v3 = fabsf(c[mi][ni][3]);
                float l0 = __ldg(&lp[m]), l1 = __ldg(&lp[m + 1]);
                p[mi][0] += v0 * l0 + v1 * l1;
                p[mi][1] += v2 * l0 + v3 * l1;
            }
        }
        #pragma unroll
        for (int mi = 0; mi < 2; mi++) {
            #pragma unroll
            for (int s = 0; s < 2; s++) {
                float v = p[mi][s];
                v += __shfl_xor_sync(0xffffffffu, v, 1);
                v += __shfl_xor_sync(0xffffffffu, v, 2);
                if (t == 0) {
                    const int r = m0 + wm * 32 + mi * 16 + g + s * 8;
                    int b = r >> 6, j1 = (r >> 4) & 3, f = r & 15;
                    atomicAdd(&phi[(b * FF + f) * NCOLS + 5 + j1 * 4 + j], v);
                }
            }
        }
    }
}

// ---------------- launch ----------------
extern "C" void kernel_launch(void* const* d_in, const int* in_sizes, int n_in,
                              void* d_out, int out_size) {
    const float* x   = (const float*)d_in[0];   // (8,16,2048)
    const float* psi = (const float*)d_in[1];   // (4,2048,2048)
    const float* lp  = (const float*)d_in[2];   // (2048,)
    float* out = (float*)d_out;                 // (8,16,21)
    (void)in_sizes; (void)n_in; (void)out_size;

    constexpr int SM1 = 2 * (2 * 128 * 80 + 2 * 64 * 80);    // 61440 (NI=4)
    constexpr int SM2 = 2 * (2 * 128 * 80 + 2 * 128 * 80);   // 81920 (NI=8)
    cudaFuncSetAttribute(gemm_f16<1, 4>, cudaFuncAttributeMaxDynamicSharedMemorySize, SM1);
    cudaFuncSetAttribute(gemm_f16<2, 8>, cudaFuncAttributeMaxDynamicSharedMemorySize, SM2);

    prep_kernel<<<BB * FF, 256>>>(x, lp, out);
    transpose_pack_psi<<<dim3(32, 32, JS), 256>>>(psi);
    // layer 1 split-K: 32 N-tiles x 2 k-halves x 4 j = 256 CTAs
    gemm_f16<1, 4><<<dim3(32, 2, 4), 256, SM1>>>(lp, out);
    pack_s1<<<512, 256>>>(lp, out);
    // layer 2: 16 N-tiles x 4 M-tiles x 4 j = 256 CTAs
    gemm_f16<2, 8><<<dim3(16, 4, 4), 256, SM2>>>(lp, out);
}